// round 1
// baseline (speedup 1.0000x reference)
#include <cuda_runtime.h>
#include <cuda_bf16.h>
#include <math.h>

// Problem constants (fixed by the reference):
//   N=200000 nodes, K_IN=8, K_OUT=4, E=800000 edges, D=64, H=128, O=1
#define MAX_N 200000
#define D_DIM 64
#define K_IN 8
#define K_OUT 4
#define H_DIM 128

// Scratch for pooled attention context [N, 64] (device global: allocation-rule safe)
__device__ float g_pooled[MAX_N * D_DIM];

// ---------------------------------------------------------------------------
// f32x2 packed-FMA helpers (sm_103a: scalar FFMA is half-rate; FFMA2 is full)
// ---------------------------------------------------------------------------
__device__ __forceinline__ unsigned long long pack2(float x, float y) {
    unsigned long long r;
    asm("mov.b64 %0, {%1, %2};" : "=l"(r) : "f"(x), "f"(y));
    return r;
}
__device__ __forceinline__ unsigned long long ffma2(unsigned long long a,
                                                    unsigned long long b,
                                                    unsigned long long c) {
    unsigned long long d;
    asm("fma.rn.f32x2 %0, %1, %2, %3;" : "=l"(d) : "l"(a), "l"(b), "l"(c));
    return d;
}
__device__ __forceinline__ float2 unpack2(unsigned long long v) {
    float2 r;
    asm("mov.b64 {%0, %1}, %2;" : "=f"(r.x), "=f"(r.y) : "l"(v));
    return r;
}

// ---------------------------------------------------------------------------
// Kernel 1: per-node self-attention over in-edges + pooled context
// One warp per node; 8 warps (256 threads) per block.
//
// Math note: pooled[d] = (1/denom) * sum_k w[k] * Ein[k][d],
//            w[k] = sum_{q: in_mask[q]} attn[q][k]
// so att_out never needs to be materialized.
// ---------------------------------------------------------------------------
__global__ void __launch_bounds__(256) attn_pool_kernel(
    const float* __restrict__ edges,
    const int* __restrict__ in_idx,
    const int* __restrict__ in_mask,
    int N)
{
    // padded rows: 68 floats per edge row -> conflict-free float4 column reads
    __shared__ float sE[8][K_IN * 68];

    const int lane = threadIdx.x & 31;
    const int w    = threadIdx.x >> 5;
    const int node = blockIdx.x * 8 + w;
    if (node >= N) return;

    float* sEw = &sE[w][0];

    // lanes 0..7 read this node's idx/mask
    int idx_l = 0, m_l = 0;
    if (lane < K_IN) {
        idx_l = in_idx[(size_t)node * K_IN + lane];
        m_l   = in_mask[(size_t)node * K_IN + lane];
    }

    // gather Ein rows: coalesced float2 per lane; keep register copy r[k]
    float2 r[K_IN];
#pragma unroll
    for (int k = 0; k < K_IN; ++k) {
        int ek = __shfl_sync(0xffffffffu, idx_l, k);
        float2 v = *(const float2*)(edges + (size_t)ek * D_DIM + lane * 2);
        r[k] = v;
        *(float2*)(sEw + k * 68 + lane * 2) = v;
    }
    __syncwarp();

    // scores: each lane computes pairs p0=lane, p1=lane+32
    //   p0: q0 = lane>>3, k = lane&7 ;  p1: q1 = q0+4, same k
    const int q0 = lane >> 3;
    const int kk = lane & 7;
    const float4* Eq0 = (const float4*)(sEw + q0 * 68);
    const float4* Eq1 = (const float4*)(sEw + (q0 + 4) * 68);
    const float4* Ekp = (const float4*)(sEw + kk * 68);

    float s0 = 0.f, s1 = 0.f;
#pragma unroll
    for (int d4 = 0; d4 < 16; ++d4) {
        float4 b  = Ekp[d4];
        float4 a0 = Eq0[d4];
        float4 a1 = Eq1[d4];
        s0 += a0.x * b.x + a0.y * b.y + a0.z * b.z + a0.w * b.w;
        s1 += a1.x * b.x + a1.y * b.y + a1.z * b.z + a1.w * b.w;
    }
    s0 *= 0.125f;   // 1/sqrt(64)
    s1 *= 0.125f;

    // key mask
    int mk = __shfl_sync(0xffffffffu, m_l, kk);
    if (!mk) { s0 = -1e9f; s1 = -1e9f; }

    // softmax over k within each 8-lane group (bits 0..2)
    float mx0 = s0, mx1 = s1;
#pragma unroll
    for (int o = 1; o < 8; o <<= 1) {
        mx0 = fmaxf(mx0, __shfl_xor_sync(0xffffffffu, mx0, o));
        mx1 = fmaxf(mx1, __shfl_xor_sync(0xffffffffu, mx1, o));
    }
    float e0 = __expf(s0 - mx0);
    float e1 = __expf(s1 - mx1);
    float z0 = e0, z1 = e1;
#pragma unroll
    for (int o = 1; o < 8; o <<= 1) {
        z0 += __shfl_xor_sync(0xffffffffu, z0, o);
        z1 += __shfl_xor_sync(0xffffffffu, z1, o);
    }
    float a0 = e0 / z0;   // attn[q0][kk]
    float a1 = e1 / z1;   // attn[q0+4][kk]

    // query masks for q0 and q0+4
    int mq0 = __shfl_sync(0xffffffffu, m_l, q0);
    int mq1 = __shfl_sync(0xffffffffu, m_l, q0 + 4);

    // w[k] = sum over valid queries of attn[q][k]; reduce over bits 3,4
    float v = (mq0 ? a0 : 0.f) + (mq1 ? a1 : 0.f);
    v += __shfl_xor_sync(0xffffffffu, v, 8);
    v += __shfl_xor_sync(0xffffffffu, v, 16);
    // every lane now holds w[lane & 7]

    // denom = max(count of valid queries, 1)
    int cnt = m_l;
#pragma unroll
    for (int o = 1; o < 32; o <<= 1)
        cnt += __shfl_xor_sync(0xffffffffu, cnt, o);
    float inv_denom = 1.f / fmaxf((float)cnt, 1.f);

    // pooled[2*lane .. 2*lane+1] = (sum_k w[k] * Ein[k][d]) / denom
    float px = 0.f, py = 0.f;
#pragma unroll
    for (int k = 0; k < K_IN; ++k) {
        float wk = __shfl_sync(0xffffffffu, v, k);
        px += wk * r[k].x;
        py += wk * r[k].y;
    }
    float2 p2 = make_float2(px * inv_denom, py * inv_denom);
    *(float2*)(g_pooled + (size_t)node * D_DIM + lane * 2) = p2;
}

// ---------------------------------------------------------------------------
// Kernel 2: fused 3-layer MLP over M = N*K_OUT rows.
//   x[128] = [edges[out_idx[row]] | pooled[row/4]]
//   y = Wout . relu(W1 . relu(W0 . x + b0) + b1) + bout, masked
// Tile: 64 rows per block, 256 threads, 4x8 micro-tile, FFMA2 accumulators.
// ---------------------------------------------------------------------------
#define MT 64
#define SX 132                      // padded X row stride (floats)
#define SMEM_FLOATS (MT * SX + H_DIM * H_DIM)

__global__ void __launch_bounds__(256, 2) mlp_kernel(
    const float* __restrict__ edges,
    const int* __restrict__ out_idx,
    const int* __restrict__ out_mask,
    const float* __restrict__ W0,
    const float* __restrict__ b0,
    const float* __restrict__ W1,
    const float* __restrict__ b1,
    const float* __restrict__ Wout,
    const float* __restrict__ bout,
    float* __restrict__ out,
    int M)
{
    extern __shared__ float smem[];
    float* Xs = smem;               // [MT][SX], cols 0..127 used
    float* Ws = smem + MT * SX;     // [128][128] transposed weights [k][h]

    const int t  = threadIdx.x;
    const int tx = t & 15;          // 16 column groups (8 h each)
    const int ty = t >> 4;          // 16 row groups (4 m each)
    const long base = (long)blockIdx.x * MT;

    // ---- load X tile: 16 threads per row, coalesced float4 ----
    {
        const int tg = t & 15;
        const int m0 = t >> 4;
#pragma unroll
        for (int rr = 0; rr < 4; ++rr) {
            int m = m0 + 16 * rr;
            long row = base + m;
            if (row < M) {
                int eidx = out_idx[row];
                long n = row >> 2;   // K_OUT = 4
                float4 e4 = *(const float4*)(edges + (size_t)eidx * D_DIM + tg * 4);
                float4 p4 = *(const float4*)(g_pooled + (size_t)n * D_DIM + tg * 4);
                *(float4*)(Xs + m * SX + tg * 4)          = e4;
                *(float4*)(Xs + m * SX + D_DIM + tg * 4)  = p4;
            } else {
                float4 z = make_float4(0.f, 0.f, 0.f, 0.f);
                *(float4*)(Xs + m * SX + tg * 4)          = z;
                *(float4*)(Xs + m * SX + D_DIM + tg * 4)  = z;
            }
        }
    }

    // ---- load W0 transposed into Ws[k][h] ----
    {
        const int h = t & 127;
        const int half = t >> 7;
#pragma unroll
        for (int it = 0; it < 16; ++it) {
            int k = half * 4 + it * 8;
            float4 wv = *(const float4*)(W0 + (size_t)h * H_DIM + k);
            Ws[(k + 0) * H_DIM + h] = wv.x;
            Ws[(k + 1) * H_DIM + h] = wv.y;
            Ws[(k + 2) * H_DIM + h] = wv.z;
            Ws[(k + 3) * H_DIM + h] = wv.w;
        }
    }
    __syncthreads();

    // ---- GEMM 1: H0[m][h] = sum_k X[m][k] * W0[h][k] ----
    unsigned long long acc[4][4];
#pragma unroll
    for (int i = 0; i < 4; ++i)
#pragma unroll
        for (int p = 0; p < 4; ++p) acc[i][p] = 0ULL;

    const float* xr0 = Xs + (4 * ty + 0) * SX;
    const float* xr1 = Xs + (4 * ty + 1) * SX;
    const float* xr2 = Xs + (4 * ty + 2) * SX;
    const float* xr3 = Xs + (4 * ty + 3) * SX;

#pragma unroll 8
    for (int k = 0; k < H_DIM; ++k) {
        ulonglong2 bu0 = *(const ulonglong2*)(Ws + k * H_DIM + 8 * tx);
        ulonglong2 bu1 = *(const ulonglong2*)(Ws + k * H_DIM + 8 * tx + 4);
        unsigned long long a0 = pack2(xr0[k], xr0[k]);
        unsigned long long a1 = pack2(xr1[k], xr1[k]);
        unsigned long long a2 = pack2(xr2[k], xr2[k]);
        unsigned long long a3 = pack2(xr3[k], xr3[k]);
        acc[0][0] = ffma2(a0, bu0.x, acc[0][0]);
        acc[0][1] = ffma2(a0, bu0.y, acc[0][1]);
        acc[0][2] = ffma2(a0, bu1.x, acc[0][2]);
        acc[0][3] = ffma2(a0, bu1.y, acc[0][3]);
        acc[1][0] = ffma2(a1, bu0.x, acc[1][0]);
        acc[1][1] = ffma2(a1, bu0.y, acc[1][1]);
        acc[1][2] = ffma2(a1, bu1.x, acc[1][2]);
        acc[1][3] = ffma2(a1, bu1.y, acc[1][3]);
        acc[2][0] = ffma2(a2, bu0.x, acc[2][0]);
        acc[2][1] = ffma2(a2, bu0.y, acc[2][1]);
        acc[2][2] = ffma2(a2, bu1.x, acc[2][2]);
        acc[2][3] = ffma2(a2, bu1.y, acc[2][3]);
        acc[3][0] = ffma2(a3, bu0.x, acc[3][0]);
        acc[3][1] = ffma2(a3, bu0.y, acc[3][1]);
        acc[3][2] = ffma2(a3, bu1.x, acc[3][2]);
        acc[3][3] = ffma2(a3, bu1.y, acc[3][3]);
    }

    // bias fragments for layer 0
    float4 bb0a = *(const float4*)(b0 + 8 * tx);
    float4 bb0b = *(const float4*)(b0 + 8 * tx + 4);
    float bj0[8] = {bb0a.x, bb0a.y, bb0a.z, bb0a.w, bb0b.x, bb0b.y, bb0b.z, bb0b.w};

    __syncthreads();  // everyone done reading Xs/Ws

    // ---- epilogue 1: relu(acc + b0) -> H0 into Xs[m][h] ----
#pragma unroll
    for (int i = 0; i < 4; ++i) {
#pragma unroll
        for (int p = 0; p < 4; ++p) {
            float2 vv = unpack2(acc[i][p]);
            vv.x = fmaxf(vv.x + bj0[2 * p], 0.f);
            vv.y = fmaxf(vv.y + bj0[2 * p + 1], 0.f);
            *(float2*)(Xs + (4 * ty + i) * SX + 8 * tx + 2 * p) = vv;
        }
    }

    // ---- load W1 transposed ----
    {
        const int h = t & 127;
        const int half = t >> 7;
#pragma unroll
        for (int it = 0; it < 16; ++it) {
            int k = half * 4 + it * 8;
            float4 wv = *(const float4*)(W1 + (size_t)h * H_DIM + k);
            Ws[(k + 0) * H_DIM + h] = wv.x;
            Ws[(k + 1) * H_DIM + h] = wv.y;
            Ws[(k + 2) * H_DIM + h] = wv.z;
            Ws[(k + 3) * H_DIM + h] = wv.w;
        }
    }
    __syncthreads();

    // ---- GEMM 2: H1[m][g] = sum_h H0[m][h] * W1[g][h] ----
#pragma unroll
    for (int i = 0; i < 4; ++i)
#pragma unroll
        for (int p = 0; p < 4; ++p) acc[i][p] = 0ULL;

#pragma unroll 8
    for (int k = 0; k < H_DIM; ++k) {
        ulonglong2 bu0 = *(const ulonglong2*)(Ws + k * H_DIM + 8 * tx);
        ulonglong2 bu1 = *(const ulonglong2*)(Ws + k * H_DIM + 8 * tx + 4);
        unsigned long long a0 = pack2(xr0[k], xr0[k]);
        unsigned long long a1 = pack2(xr1[k], xr1[k]);
        unsigned long long a2 = pack2(xr2[k], xr2[k]);
        unsigned long long a3 = pack2(xr3[k], xr3[k]);
        acc[0][0] = ffma2(a0, bu0.x, acc[0][0]);
        acc[0][1] = ffma2(a0, bu0.y, acc[0][1]);
        acc[0][2] = ffma2(a0, bu1.x, acc[0][2]);
        acc[0][3] = ffma2(a0, bu1.y, acc[0][3]);
        acc[1][0] = ffma2(a1, bu0.x, acc[1][0]);
        acc[1][1] = ffma2(a1, bu0.y, acc[1][1]);
        acc[1][2] = ffma2(a1, bu1.x, acc[1][2]);
        acc[1][3] = ffma2(a1, bu1.y, acc[1][3]);
        acc[2][0] = ffma2(a2, bu0.x, acc[2][0]);
        acc[2][1] = ffma2(a2, bu0.y, acc[2][1]);
        acc[2][2] = ffma2(a2, bu1.x, acc[2][2]);
        acc[2][3] = ffma2(a2, bu1.y, acc[2][3]);
        acc[3][0] = ffma2(a3, bu0.x, acc[3][0]);
        acc[3][1] = ffma2(a3, bu0.y, acc[3][1]);
        acc[3][2] = ffma2(a3, bu1.x, acc[3][2]);
        acc[3][3] = ffma2(a3, bu1.y, acc[3][3]);
    }

    // ---- epilogue 2: relu(+b1), dot with Wout, reduce over tx, store ----
    float4 bb1a = *(const float4*)(b1 + 8 * tx);
    float4 bb1b = *(const float4*)(b1 + 8 * tx + 4);
    float bj1[8] = {bb1a.x, bb1a.y, bb1a.z, bb1a.w, bb1b.x, bb1b.y, bb1b.z, bb1b.w};
    float4 woa = *(const float4*)(Wout + 8 * tx);
    float4 wob = *(const float4*)(Wout + 8 * tx + 4);
    float wo[8] = {woa.x, woa.y, woa.z, woa.w, wob.x, wob.y, wob.z, wob.w};
    float boutv = bout[0];

#pragma unroll
    for (int i = 0; i < 4; ++i) {
        float y = 0.f;
#pragma unroll
        for (int p = 0; p < 4; ++p) {
            float2 vv = unpack2(acc[i][p]);
            float hx = fmaxf(vv.x + bj1[2 * p], 0.f);
            float hy = fmaxf(vv.y + bj1[2 * p + 1], 0.f);
            y += wo[2 * p] * hx + wo[2 * p + 1] * hy;
        }
#pragma unroll
        for (int o = 1; o < 16; o <<= 1)
            y += __shfl_xor_sync(0xffffffffu, y, o);
        if (tx == 0) {
            long row = base + 4 * ty + i;
            if (row < M) {
                float om = (float)out_mask[row];
                out[row] = (y + boutv) * om;
            }
        }
    }
}

// ---------------------------------------------------------------------------
extern "C" void kernel_launch(void* const* d_in, const int* in_sizes, int n_in,
                              void* d_out, int out_size) {
    const float* edges   = (const float*)d_in[0];
    const int*   in_idx  = (const int*)d_in[1];
    const int*   in_mask = (const int*)d_in[2];
    const int*   out_idx = (const int*)d_in[3];
    const int*   out_mask= (const int*)d_in[4];
    const float* W0      = (const float*)d_in[5];
    const float* b0      = (const float*)d_in[6];
    const float* W1      = (const float*)d_in[7];
    const float* b1      = (const float*)d_in[8];
    const float* Wout    = (const float*)d_in[9];
    const float* bout    = (const float*)d_in[10];
    float* out = (float*)d_out;

    int N = in_sizes[1] / K_IN;     // 200000
    int M = N * K_OUT;              // 800000

    attn_pool_kernel<<<(N + 7) / 8, 256>>>(edges, in_idx, in_mask, N);

    size_t smem_bytes = (size_t)SMEM_FLOATS * sizeof(float);   // 99328
    cudaFuncSetAttribute(mlp_kernel,
                         cudaFuncAttributeMaxDynamicSharedMemorySize,
                         (int)smem_bytes);
    mlp_kernel<<<(M + MT - 1) / MT, 256, smem_bytes>>>(
        edges, out_idx, out_mask, W0, b0, W1, b1, Wout, bout, out, M);
}